// round 1
// baseline (speedup 1.0000x reference)
#include <cuda_runtime.h>
#include <math.h>

#define BATCH   2
#define SEQ     2048
#define DMODEL  2048
#define NHEADS  16
#define DK      128
#define MTOT    (BATCH * SEQ)   // 4096

// ---------------- scratch (device globals: no allocation allowed) ----------------
__device__ float g_q [(size_t)MTOT * DMODEL];
__device__ float g_k [(size_t)MTOT * DMODEL];
__device__ float g_v [(size_t)MTOT * DMODEL];
__device__ float g_ao[(size_t)MTOT * DMODEL];
__device__ float g_cos[SEQ * (DK / 2)];
__device__ float g_sin[SEQ * (DK / 2)];

// ---------------- RoPE table: accurate sin/cos of the fp32 angle ----------------
__global__ void rope_table_kernel(const int* __restrict__ tp) {
    int idx = blockIdx.x * blockDim.x + threadIdx.x;
    if (idx >= SEQ * (DK / 2)) return;
    int s = idx / (DK / 2);
    int i = idx % (DK / 2);
    // match reference: inv_freq computed in fp32, angle = fp32(pos) * fp32(inv_freq)
    float ex   = (float)(2 * i) / (float)DK;
    float invf = 1.0f / powf(10000.0f, ex);
    float angf = (float)tp[s] * invf;
    // reference (XLA) evaluates cos/sin of that fp32 angle accurately -> use fp64
    double a = (double)angf;
    g_cos[idx] = (float)cos(a);
    g_sin[idx] = (float)sin(a);
}

// ---------------- C[M,N] = A[M,K] @ B[N,K]^T  (fp32, optional fused RoPE) -------
// 128x128 block tile, BK=8, 256 threads, 8x8 per thread.
template<bool ROPE>
__global__ __launch_bounds__(256, 2) void gemm_nt(
    const float* __restrict__ A, const float* __restrict__ B,
    float* __restrict__ C, int M, int N, int K)
{
    __shared__ __align__(16) float As[8 * 132];
    __shared__ __align__(16) float Bs[8 * 132];

    const int tid  = threadIdx.x;
    const int row0 = blockIdx.y * 128;
    const int col0 = blockIdx.x * 128;

    // warp/lane tiling: 8 warps as 4x2, each warp 32x64, lanes as 4x8 of 8x8 tiles
    const int w      = tid >> 5;
    const int lane   = tid & 31;
    const int rowOff = (w & 3) * 32 + (lane & 3) * 8;
    const int colOff = (w >> 2) * 64 + (lane >> 2) * 8;

    // tile loaders: one float4 per thread per tile
    const int ldRow = tid >> 1;
    const int ldK   = (tid & 1) * 4;
    const float* Ap = A + (size_t)(row0 + ldRow) * K + ldK;
    const float* Bp = B + (size_t)(col0 + ldRow) * K + ldK;

    float acc[8][8];
#pragma unroll
    for (int i = 0; i < 8; ++i)
#pragma unroll
        for (int j = 0; j < 8; ++j) acc[i][j] = 0.f;

    float4 aNext = *(const float4*)Ap;
    float4 bNext = *(const float4*)Bp;

    for (int kk = 0; kk < K; kk += 8) {
        As[(ldK + 0) * 132 + ldRow] = aNext.x;
        As[(ldK + 1) * 132 + ldRow] = aNext.y;
        As[(ldK + 2) * 132 + ldRow] = aNext.z;
        As[(ldK + 3) * 132 + ldRow] = aNext.w;
        Bs[(ldK + 0) * 132 + ldRow] = bNext.x;
        Bs[(ldK + 1) * 132 + ldRow] = bNext.y;
        Bs[(ldK + 2) * 132 + ldRow] = bNext.z;
        Bs[(ldK + 3) * 132 + ldRow] = bNext.w;
        __syncthreads();

        if (kk + 8 < K) {  // register prefetch of next k-slab
            aNext = *(const float4*)(Ap + kk + 8);
            bNext = *(const float4*)(Bp + kk + 8);
        }

#pragma unroll
        for (int k = 0; k < 8; ++k) {
            float4 a0 = *(const float4*)(As + k * 132 + rowOff);
            float4 a1 = *(const float4*)(As + k * 132 + rowOff + 4);
            float4 b0 = *(const float4*)(Bs + k * 132 + colOff);
            float4 b1 = *(const float4*)(Bs + k * 132 + colOff + 4);
            float ar[8] = {a0.x, a0.y, a0.z, a0.w, a1.x, a1.y, a1.z, a1.w};
            float br[8] = {b0.x, b0.y, b0.z, b0.w, b1.x, b1.y, b1.z, b1.w};
#pragma unroll
            for (int i = 0; i < 8; ++i)
#pragma unroll
                for (int j = 0; j < 8; ++j)
                    acc[i][j] += ar[i] * br[j];
        }
        __syncthreads();
    }

#pragma unroll
    for (int i = 0; i < 8; ++i) {
        int r = row0 + rowOff + i;
        float out[8];
#pragma unroll
        for (int j = 0; j < 8; ++j) out[j] = acc[i][j];
        if (ROPE) {
            int pos = r & (SEQ - 1);
#pragma unroll
            for (int jp = 0; jp < 8; jp += 2) {
                int col = col0 + colOff + jp;
                int pr  = (col & (DK - 1)) >> 1;
                float cs = g_cos[pos * (DK / 2) + pr];
                float sn = g_sin[pos * (DK / 2) + pr];
                float x1 = out[jp], x2 = out[jp + 1];
                out[jp]     = x1 * cs - x2 * sn;
                out[jp + 1] = x1 * sn + x2 * cs;
            }
        }
        float* Cp = C + (size_t)r * N + col0 + colOff;
        *(float4*)(Cp)     = make_float4(out[0], out[1], out[2], out[3]);
        *(float4*)(Cp + 4) = make_float4(out[4], out[5], out[6], out[7]);
    }
}

// ---------------- causal flash attention, fp32, Bq=Bk=64, Dk=128 ----------------
// 256 threads: ty=tid/16 owns 4 q-rows, tx=tid%16.
// S tile: thread computes s[4][4] for k columns (tx + 16*j).
// O tile: thread owns O[4][8] for d columns (tx + 16*jd).
__global__ __launch_bounds__(256) void attn_kernel(
    const float* __restrict__ Q, const float* __restrict__ Kg,
    const float* __restrict__ Vg, float* __restrict__ Og)
{
    extern __shared__ __align__(16) float sm[];
    float* Qs = sm;                 // 64 x 132
    float* Ks = Qs + 64 * 132;      // 64 x 132
    float* Vs = Ks + 64 * 132;      // 64 x 128
    float* Ps = Vs + 64 * 128;      // 64 x 68

    const int tid = threadIdx.x;
    const int tx  = tid & 15;
    const int ty  = tid >> 4;
    const int qb  = blockIdx.x;
    const int bh  = blockIdx.y;
    const int b   = bh >> 4;
    const int h   = bh & 15;
    const int q0  = qb * 64;
    const size_t base = (size_t)b * SEQ * DMODEL + (size_t)h * DK;

    // load Q tile
    for (int f = tid; f < 64 * 32; f += 256) {
        int r = f >> 5, c4 = (f & 31) << 2;
        *(float4*)(Qs + r * 132 + c4) =
            *(const float4*)(Q + base + (size_t)(q0 + r) * DMODEL + c4);
    }

    float m_i[4], l_i[4], O[4][8];
#pragma unroll
    for (int i = 0; i < 4; ++i) {
        m_i[i] = -1e30f;
        l_i[i] = 0.f;
#pragma unroll
        for (int jd = 0; jd < 8; ++jd) O[i][jd] = 0.f;
    }
    const float scale = 0.08838834764831845f;  // 1/sqrt(128)

    for (int kb = 0; kb <= qb; ++kb) {
        const int k0 = kb * 64;
        __syncthreads();  // prior P@V done before overwriting K/V
        for (int f = tid; f < 64 * 32; f += 256) {
            int r = f >> 5, c4 = (f & 31) << 2;
            *(float4*)(Ks + r * 132 + c4) =
                *(const float4*)(Kg + base + (size_t)(k0 + r) * DMODEL + c4);
            *(float4*)(Vs + r * 128 + c4) =
                *(const float4*)(Vg + base + (size_t)(k0 + r) * DMODEL + c4);
        }
        __syncthreads();

        float s[4][4];
#pragma unroll
        for (int i = 0; i < 4; ++i)
#pragma unroll
            for (int j = 0; j < 4; ++j) s[i][j] = 0.f;

#pragma unroll 8
        for (int d4 = 0; d4 < 32; ++d4) {
            float4 kvv[4], qvv[4];
#pragma unroll
            for (int j = 0; j < 4; ++j)
                kvv[j] = *(const float4*)(Ks + (tx + 16 * j) * 132 + 4 * d4);
#pragma unroll
            for (int i = 0; i < 4; ++i)
                qvv[i] = *(const float4*)(Qs + (ty * 4 + i) * 132 + 4 * d4);
#pragma unroll
            for (int i = 0; i < 4; ++i)
#pragma unroll
                for (int j = 0; j < 4; ++j)
                    s[i][j] += qvv[i].x * kvv[j].x + qvv[i].y * kvv[j].y +
                               qvv[i].z * kvv[j].z + qvv[i].w * kvv[j].w;
        }

        const bool diag = (kb == qb);
#pragma unroll
        for (int i = 0; i < 4; ++i) {
            const int qg = q0 + ty * 4 + i;
            float mx = -1e30f;
#pragma unroll
            for (int j = 0; j < 4; ++j) {
                float sv = s[i][j] * scale;
                if (diag && (k0 + tx + 16 * j > qg)) sv = -1e30f;
                s[i][j] = sv;
                mx = fmaxf(mx, sv);
            }
#pragma unroll
            for (int off = 8; off > 0; off >>= 1)
                mx = fmaxf(mx, __shfl_xor_sync(0xffffffffu, mx, off));

            float mnew  = fmaxf(m_i[i], mx);
            float alpha = __expf(m_i[i] - mnew);
            float psum  = 0.f;
#pragma unroll
            for (int j = 0; j < 4; ++j) {
                float p = __expf(s[i][j] - mnew);
                Ps[(ty * 4 + i) * 68 + tx + 16 * j] = p;
                psum += p;
            }
#pragma unroll
            for (int off = 8; off > 0; off >>= 1)
                psum += __shfl_xor_sync(0xffffffffu, psum, off);

            l_i[i] = l_i[i] * alpha + psum;
            m_i[i] = mnew;
#pragma unroll
            for (int jd = 0; jd < 8; ++jd) O[i][jd] *= alpha;
        }
        __syncthreads();

        // O += P @ V
#pragma unroll 4
        for (int kk = 0; kk < 64; ++kk) {
            float pv[4];
#pragma unroll
            for (int i = 0; i < 4; ++i) pv[i] = Ps[(ty * 4 + i) * 68 + kk];
#pragma unroll
            for (int jd = 0; jd < 8; ++jd) {
                float vv = Vs[kk * 128 + tx + 16 * jd];
#pragma unroll
                for (int i = 0; i < 4; ++i) O[i][jd] += pv[i] * vv;
            }
        }
    }

#pragma unroll
    for (int i = 0; i < 4; ++i) {
        float inv = 1.0f / l_i[i];
        size_t rowb = ((size_t)b * SEQ + q0 + ty * 4 + i) * DMODEL + (size_t)h * DK;
#pragma unroll
        for (int jd = 0; jd < 8; ++jd)
            Og[rowb + tx + 16 * jd] = O[i][jd] * inv;
    }
}

// ---------------------------------------------------------------------------------
extern "C" void kernel_launch(void* const* d_in, const int* in_sizes, int n_in,
                              void* d_out, int out_size)
{
    const float* x  = (const float*)d_in[0];
    const int*   tp = (const int*)  d_in[1];
    const float* wq = (const float*)d_in[2];
    const float* wk = (const float*)d_in[3];
    const float* wv = (const float*)d_in[4];
    const float* wo = (const float*)d_in[5];
    float* out = (float*)d_out;

    float *qp, *kp, *vp, *aop;
    cudaGetSymbolAddress((void**)&qp,  g_q);
    cudaGetSymbolAddress((void**)&kp,  g_k);
    cudaGetSymbolAddress((void**)&vp,  g_v);
    cudaGetSymbolAddress((void**)&aop, g_ao);

    rope_table_kernel<<<(SEQ * (DK / 2) + 255) / 256, 256>>>(tp);

    dim3 gg(DMODEL / 128, MTOT / 128);
    gemm_nt<true ><<<gg, 256>>>(x, wq, qp, MTOT, DMODEL, DMODEL);
    gemm_nt<true ><<<gg, 256>>>(x, wk, kp, MTOT, DMODEL, DMODEL);
    gemm_nt<false><<<gg, 256>>>(x, wv, vp, MTOT, DMODEL, DMODEL);

    const int ATTN_SMEM = (64 * 132 + 64 * 132 + 64 * 128 + 64 * 68) * 4;
    cudaFuncSetAttribute(attn_kernel, cudaFuncAttributeMaxDynamicSharedMemorySize,
                         ATTN_SMEM);
    attn_kernel<<<dim3(SEQ / 64, BATCH * NHEADS), 256, ATTN_SMEM>>>(qp, kp, vp, aop);

    gemm_nt<false><<<gg, 256>>>(aop, wo, out, MTOT, DMODEL, DMODEL);
}